// round 5
// baseline (speedup 1.0000x reference)
#include <cuda_runtime.h>
#include <cuda_bf16.h>
#include <math.h>
#include <stdint.h>

// Problem dims (fixed by the dataset)
#define BB 2
#define SS 2048
#define HH 1024
#define NHEAD 16
#define HD 64
#define MM (BB*SS)          // 4096 rows

// ---------------------------------------------------------------------------
// Scratch (device globals: allocation-free rule)
// ---------------------------------------------------------------------------
__device__ float g_Q[MM * HH];
__device__ float g_K[MM * HH];
__device__ float g_V[MM * HH];
__device__ float g_C[MM * HH];
__device__ float g_cos[SS * 32];
__device__ float g_sin[SS * 32];
__device__ __nv_bfloat16 g_Xhi[MM * HH];
__device__ __nv_bfloat16 g_Xlo[MM * HH];
__device__ __nv_bfloat16 g_Chi[MM * HH];
__device__ __nv_bfloat16 g_Clo[MM * HH];
__device__ __nv_bfloat16 g_Whi[4 * HH * HH];   // W^T hi, [N,K] per weight
__device__ __nv_bfloat16 g_Wlo[4 * HH * HH];   // W^T lo

// ---------------------------------------------------------------------------
// PTX helpers (sm_80-baseline features only: ldmatrix / mma.sync / cp.async)
// ---------------------------------------------------------------------------
__device__ __forceinline__ uint32_t smem_u32(const void* p) {
    uint32_t a;
    asm("{ .reg .u64 t; cvta.to.shared.u64 t, %1; cvt.u32.u64 %0, t; }" : "=r"(a) : "l"(p));
    return a;
}
#define CP_ASYNC16(s, g) \
    asm volatile("cp.async.cg.shared.global [%0], [%1], 16;" :: "r"(s), "l"(g))
#define CP_COMMIT() asm volatile("cp.async.commit_group;" ::: "memory")
#define CP_WAIT1()  asm volatile("cp.async.wait_group 1;" ::: "memory")

__device__ __forceinline__ void ldsm_x4(uint32_t* r, uint32_t addr) {
    asm volatile("ldmatrix.sync.aligned.m8n8.x4.shared.b16 {%0,%1,%2,%3}, [%4];"
                 : "=r"(r[0]), "=r"(r[1]), "=r"(r[2]), "=r"(r[3]) : "r"(addr));
}
// B tile is [N,K] row-major (= col-major KxN): NON-trans x2 gives the b
// fragment directly (fragment row = n = lane/4, reg pair consecutive in k).
__device__ __forceinline__ void ldsm_x2(uint32_t* r, uint32_t addr) {
    asm volatile("ldmatrix.sync.aligned.m8n8.x2.shared.b16 {%0,%1}, [%2];"
                 : "=r"(r[0]), "=r"(r[1]) : "r"(addr));
}
__device__ __forceinline__ void mma_bf16(float* c, const uint32_t* a, const uint32_t* b) {
    asm volatile("mma.sync.aligned.m16n8k16.row.col.f32.bf16.bf16.f32 "
                 "{%0,%1,%2,%3}, {%4,%5,%6,%7}, {%8,%9}, {%0,%1,%2,%3};"
                 : "+f"(c[0]), "+f"(c[1]), "+f"(c[2]), "+f"(c[3])
                 : "r"(a[0]), "r"(a[1]), "r"(a[2]), "r"(a[3]), "r"(b[0]), "r"(b[1]));
}

// ---------------------------------------------------------------------------
// Prep: fp32 -> (hi, lo) bf16 split
// ---------------------------------------------------------------------------
__global__ void split_kernel(const float* __restrict__ x,
                             __nv_bfloat16* __restrict__ hi,
                             __nv_bfloat16* __restrict__ lo, int n4)
{
    int i = blockIdx.x * blockDim.x + threadIdx.x;
    if (i >= n4) return;
    float4 v = reinterpret_cast<const float4*>(x)[i];
    __nv_bfloat16 h[4], l[4];
    float f[4] = {v.x, v.y, v.z, v.w};
    #pragma unroll
    for (int j = 0; j < 4; j++) {
        h[j] = __float2bfloat16(f[j]);
        l[j] = __float2bfloat16(f[j] - __bfloat162float(h[j]));
    }
    reinterpret_cast<ushort4*>(hi)[i] = make_ushort4(
        __bfloat16_as_ushort(h[0]), __bfloat16_as_ushort(h[1]),
        __bfloat16_as_ushort(h[2]), __bfloat16_as_ushort(h[3]));
    reinterpret_cast<ushort4*>(lo)[i] = make_ushort4(
        __bfloat16_as_ushort(l[0]), __bfloat16_as_ushort(l[1]),
        __bfloat16_as_ushort(l[2]), __bfloat16_as_ushort(l[3]));
}

// Transpose + split 4 weights: W[k,n] -> WT[n,k] hi/lo
__global__ void wsplit_kernel(const float* __restrict__ W0, const float* __restrict__ W1,
                              const float* __restrict__ W2, const float* __restrict__ W3)
{
    __shared__ float t[32][33];
    int w = blockIdx.z;
    const float* W = (w == 0) ? W0 : (w == 1) ? W1 : (w == 2) ? W2 : W3;
    int bn = blockIdx.x * 32;   // n block
    int bk = blockIdx.y * 32;   // k block
    int x = threadIdx.x, y = threadIdx.y;   // 32 x 8
    #pragma unroll
    for (int j = 0; j < 32; j += 8)
        t[y + j][x] = W[(size_t)(bk + y + j) * HH + bn + x];
    __syncthreads();
    size_t base = (size_t)w * HH * HH;
    #pragma unroll
    for (int j = 0; j < 32; j += 8) {
        float v = t[x][y + j];
        __nv_bfloat16 h = __float2bfloat16(v);
        __nv_bfloat16 l = __float2bfloat16(v - __bfloat162float(h));
        size_t o = base + (size_t)(bn + y + j) * HH + bk + x;
        g_Whi[o] = h;
        g_Wlo[o] = l;
    }
}

// ---------------------------------------------------------------------------
// Tensor-core GEMM (bf16x3 via mma.sync):
//   C[M,N] = A @ W + bias,  A hi/lo [M,K] row-major, B = W^T hi/lo [N,K] row-major
// CTA tile 128x128, K-chunk 32, 8 warps (each 64x32), cp.async double buffer.
// smem stage: 4 tiles of [128][40] bf16 (pad 8) = 40960 B; 2 stages = 81920 B
// ---------------------------------------------------------------------------
#define TILE_E   (128 * 40)                 // elems per tile
#define STAGE_E  (4 * TILE_E)               // elems per stage
#define GT_SMEM  (2 * STAGE_E * 2)          // bytes

__global__ void __launch_bounds__(256) tc_gemm(
    const __nv_bfloat16* __restrict__ Ahi, const __nv_bfloat16* __restrict__ Alo,
    const __nv_bfloat16* __restrict__ Bhi, const __nv_bfloat16* __restrict__ Blo,
    const float* __restrict__ bias, float* __restrict__ C)
{
    extern __shared__ __nv_bfloat16 sm[];
    const int tid  = threadIdx.x;
    const int lane = tid & 31;
    const int w    = tid >> 5;
    const int wm   = (w & 1) * 64;   // warp row offset within CTA tile
    const int wn   = (w >> 1) * 32;  // warp col offset within CTA tile
    const int rowBase = blockIdx.y * 128;
    const int colBase = blockIdx.x * 128;

    const uint32_t sb = smem_u32(sm);

    // global row bases per tile id {Ahi, Alo, Bhi, Blo}
    const __nv_bfloat16* gsel[4] = {
        Ahi + (size_t)rowBase * HH, Alo + (size_t)rowBase * HH,
        Bhi + (size_t)colBase * HH, Blo + (size_t)colBase * HH };

    // issue one stage of cp.async copies
    auto issue = [&](int st, int k0) {
        uint32_t sbase = sb + (uint32_t)(st * STAGE_E * 2);
        #pragma unroll
        for (int t = 0; t < 8; t++) {
            int i    = t * 256 + tid;        // 0..2047
            int tile = i >> 9;               // 0..3
            int r    = (i >> 2) & 127;
            int c    = i & 3;                // 16B chunk (8 bf16)
            uint32_t sa = sbase + (uint32_t)((tile * TILE_E + r * 40 + c * 8) * 2);
            const __nv_bfloat16* ga = gsel[tile] + (size_t)r * HH + k0 + c * 8;
            CP_ASYNC16(sa, ga);
        }
    };

    float acc[4][4][4];
    #pragma unroll
    for (int mt = 0; mt < 4; mt++)
        #pragma unroll
        for (int nt = 0; nt < 4; nt++)
            #pragma unroll
            for (int q = 0; q < 4; q++) acc[mt][nt][q] = 0.0f;

    issue(0, 0);
    CP_COMMIT();

    const int nIter = HH / 32;   // 32
    for (int it = 0; it < nIter; it++) {
        if (it + 1 < nIter) issue((it + 1) & 1, (it + 1) * 32);
        CP_COMMIT();
        CP_WAIT1();
        __syncthreads();

        uint32_t stage = sb + (uint32_t)((it & 1) * STAGE_E * 2);
        #pragma unroll
        for (int ks = 0; ks < 32; ks += 16) {
            #pragma unroll
            for (int combo = 0; combo < 3; combo++) {
                const int selA = (combo == 2) ? 1 : 0;       // lo A only in combo 2
                const int selB = (combo == 1) ? 1 : 0;       // lo B only in combo 1
                uint32_t abase = stage + (uint32_t)(selA * TILE_E * 2);
                uint32_t bbase = stage + (uint32_t)((2 + selB) * TILE_E * 2);

                uint32_t a[4][4];
                #pragma unroll
                for (int mt = 0; mt < 4; mt++) {
                    uint32_t addr = abase + (uint32_t)(((wm + mt * 16 + (lane & 15)) * 40
                                     + ks + ((lane >> 4) << 3)) * 2);
                    ldsm_x4(a[mt], addr);
                }
                #pragma unroll
                for (int nt = 0; nt < 4; nt++) {
                    uint32_t b[2];
                    uint32_t addr = bbase + (uint32_t)(((wn + nt * 8 + (lane & 7)) * 40
                                     + ks + (((lane >> 3) & 1) << 3)) * 2);
                    ldsm_x2(b, addr);
                    #pragma unroll
                    for (int mt = 0; mt < 4; mt++)
                        mma_bf16(acc[mt][nt], a[mt], b);
                }
            }
        }
        __syncthreads();
    }

    // epilogue: add bias, write fp32 C
    #pragma unroll
    for (int mt = 0; mt < 4; mt++) {
        int r0 = rowBase + wm + mt * 16 + (lane >> 2);
        #pragma unroll
        for (int nt = 0; nt < 4; nt++) {
            int cc = colBase + wn + nt * 8 + (lane & 3) * 2;
            float b0 = bias[cc], b1 = bias[cc + 1];
            float2 v0 = make_float2(acc[mt][nt][0] + b0, acc[mt][nt][1] + b1);
            float2 v1 = make_float2(acc[mt][nt][2] + b0, acc[mt][nt][3] + b1);
            *reinterpret_cast<float2*>(&C[(size_t)r0 * HH + cc]) = v0;
            *reinterpret_cast<float2*>(&C[(size_t)(r0 + 8) * HH + cc]) = v1;
        }
    }
}

// ---------------------------------------------------------------------------
// RoPE table + apply (unchanged, verified in R1)
// ---------------------------------------------------------------------------
__global__ void rope_table_kernel()
{
    int i = blockIdx.x * blockDim.x + threadIdx.x;
    if (i >= SS * 32) return;
    int s = i >> 5;
    int d = i & 31;
    float inv = 1.0f / powf(10000.0f, (float)d / 32.0f);
    float th  = (float)s * inv;
    g_cos[i] = (float)cos((double)th);
    g_sin[i] = (float)sin((double)th);
}

__global__ void rope_apply_kernel(float* __restrict__ Q, float* __restrict__ K)
{
    int idx = blockIdx.x * blockDim.x + threadIdx.x;
    const int total = MM * NHEAD * 32;
    if (idx >= total) return;
    int d   = idx & 31;
    int h   = (idx >> 5) & 15;
    int r   = idx >> 9;
    int s   = r & (SS - 1);
    float c  = g_cos[s * 32 + d];
    float sn = g_sin[s * 32 + d];
    size_t base = (size_t)r * HH + h * HD + d;

    float q0 = Q[base], q1 = Q[base + 32];
    Q[base]      = q0 * c - q1 * sn;
    Q[base + 32] = q1 * c + q0 * sn;

    float k0 = K[base], k1 = K[base + 32];
    K[base]      = k0 * c - k1 * sn;
    K[base + 32] = k1 * c + k0 * sn;
}

// ---------------------------------------------------------------------------
// Flash attention (unchanged, verified in R1)
// ---------------------------------------------------------------------------
#define ATTN_SMEM ((64*64 + 64*65 + 64*65 + 64*64 + 64) * 4)

__global__ void __launch_bounds__(256) attn_kernel(
    const float* __restrict__ Q, const float* __restrict__ K,
    const float* __restrict__ V, const float* __restrict__ mask,
    float* __restrict__ Ctx)
{
    extern __shared__ float smf[];
    float* Qs = smf;
    float* Ks = Qs + 64 * 64;
    float* Vs = Ks + 64 * 65;
    float* Ps = Vs + 64 * 65;
    float* Ms = Ps + 64 * 64;

    const int b  = blockIdx.z;
    const int h  = blockIdx.y;
    const int q0 = blockIdx.x * 64;
    const int tid = threadIdx.x;
    const int tx  = tid & 15;
    const int ty  = tid >> 4;

    const float* Qb = Q + (size_t)(b * SS) * HH + h * HD;
    const float* Kb = K + (size_t)(b * SS) * HH + h * HD;
    const float* Vb = V + (size_t)(b * SS) * HH + h * HD;
    const float* mb = mask + b * SS;

    for (int i = tid; i < 64 * 16; i += 256) {
        int r  = i >> 4;
        int c4 = (i & 15) << 2;
        float4 v4 = *reinterpret_cast<const float4*>(Qb + (size_t)(q0 + r) * HH + c4);
        *reinterpret_cast<float4*>(&Qs[r * 64 + c4]) = v4;
    }

    float Oacc[4][4];
    float m_run[4], l_run[4];
    #pragma unroll
    for (int i = 0; i < 4; i++) {
        m_run[i] = -1e30f;
        l_run[i] = 0.0f;
        #pragma unroll
        for (int j = 0; j < 4; j++) Oacc[i][j] = 0.0f;
    }

    const int nkt = (q0 >> 6) + 1;

    for (int kt = 0; kt < nkt; kt++) {
        const int k0 = kt * 64;
        for (int i = tid; i < 64 * 16; i += 256) {
            int r  = i >> 4;
            int c4 = (i & 15) << 2;
            float4 kv = *reinterpret_cast<const float4*>(Kb + (size_t)(k0 + r) * HH + c4);
            Ks[r * 65 + c4 + 0] = kv.x; Ks[r * 65 + c4 + 1] = kv.y;
            Ks[r * 65 + c4 + 2] = kv.z; Ks[r * 65 + c4 + 3] = kv.w;
            float4 vv = *reinterpret_cast<const float4*>(Vb + (size_t)(k0 + r) * HH + c4);
            Vs[r * 65 + c4 + 0] = vv.x; Vs[r * 65 + c4 + 1] = vv.y;
            Vs[r * 65 + c4 + 2] = vv.z; Vs[r * 65 + c4 + 3] = vv.w;
        }
        if (tid < 64) Ms[tid] = mb[k0 + tid];
        __syncthreads();

        float sacc[4][4];
        #pragma unroll
        for (int i = 0; i < 4; i++)
            #pragma unroll
            for (int j = 0; j < 4; j++) sacc[i][j] = 0.0f;

        #pragma unroll 4
        for (int d = 0; d < 64; d++) {
            float qf[4], kf[4];
            #pragma unroll
            for (int i = 0; i < 4; i++) qf[i] = Qs[(ty * 4 + i) * 64 + d];
            #pragma unroll
            for (int j = 0; j < 4; j++) kf[j] = Ks[(tx * 4 + j) * 65 + d];
            #pragma unroll
            for (int i = 0; i < 4; i++)
                #pragma unroll
                for (int j = 0; j < 4; j++)
                    sacc[i][j] = fmaf(qf[i], kf[j], sacc[i][j]);
        }

        const bool diag = (kt == nkt - 1);
        #pragma unroll
        for (int i = 0; i < 4; i++) {
            #pragma unroll
            for (int j = 0; j < 4; j++) {
                float sv = sacc[i][j] * 0.125f;
                sv += (1.0f - Ms[tx * 4 + j]) * (-1e4f);
                if (diag) {
                    int qg = q0 + ty * 4 + i;
                    int kg = k0 + tx * 4 + j;
                    if (kg > qg) sv += -1e10f;
                }
                sacc[i][j] = sv;
            }
        }

        #pragma unroll
        for (int i = 0; i < 4; i++) {
            float mm = fmaxf(fmaxf(sacc[i][0], sacc[i][1]), fmaxf(sacc[i][2], sacc[i][3]));
            #pragma unroll
            for (int off = 8; off >= 1; off >>= 1)
                mm = fmaxf(mm, __shfl_xor_sync(0xffffffffu, mm, off));
            float mnew  = fmaxf(m_run[i], mm);
            float alpha = __expf(m_run[i] - mnew);
            float ls = 0.0f;
            #pragma unroll
            for (int j = 0; j < 4; j++) {
                float p = __expf(sacc[i][j] - mnew);
                Ps[(ty * 4 + i) * 64 + tx * 4 + j] = p;
                ls += p;
            }
            #pragma unroll
            for (int off = 8; off >= 1; off >>= 1)
                ls += __shfl_xor_sync(0xffffffffu, ls, off);
            l_run[i] = l_run[i] * alpha + ls;
            m_run[i] = mnew;
            #pragma unroll
            for (int j = 0; j < 4; j++) Oacc[i][j] *= alpha;
        }
        __syncthreads();

        #pragma unroll 4
        for (int kk = 0; kk < 64; kk++) {
            float pf[4], vf[4];
            #pragma unroll
            for (int i = 0; i < 4; i++) pf[i] = Ps[(ty * 4 + i) * 64 + kk];
            #pragma unroll
            for (int j = 0; j < 4; j++) vf[j] = Vs[kk * 65 + tx * 4 + j];
            #pragma unroll
            for (int i = 0; i < 4; i++)
                #pragma unroll
                for (int j = 0; j < 4; j++)
                    Oacc[i][j] = fmaf(pf[i], vf[j], Oacc[i][j]);
        }
        __syncthreads();
    }

    float* Cb = Ctx + (size_t)(b * SS) * HH + h * HD;
    #pragma unroll
    for (int i = 0; i < 4; i++) {
        float inv_l = 1.0f / l_run[i];
        #pragma unroll
        for (int j = 0; j < 4; j++)
            Cb[(size_t)(q0 + ty * 4 + i) * HH + tx * 4 + j] = Oacc[i][j] * inv_l;
    }
}

// ---------------------------------------------------------------------------
// launcher
// ---------------------------------------------------------------------------
extern "C" void kernel_launch(void* const* d_in, const int* in_sizes, int n_in,
                              void* d_out, int out_size)
{
    const float* X    = (const float*)d_in[0];
    const float* mask = (const float*)d_in[1];
    const float* Wq   = (const float*)d_in[2];
    const float* bq   = (const float*)d_in[3];
    const float* Wk   = (const float*)d_in[4];
    const float* bk   = (const float*)d_in[5];
    const float* Wv   = (const float*)d_in[6];
    const float* bv   = (const float*)d_in[7];
    const float* Wo   = (const float*)d_in[8];
    const float* bo   = (const float*)d_in[9];
    float* out = (float*)d_out;

    float *qp, *kp, *vp, *cp;
    __nv_bfloat16 *xhi, *xlo, *chi, *clo, *whi, *wlo;
    cudaGetSymbolAddress((void**)&qp, g_Q);
    cudaGetSymbolAddress((void**)&kp, g_K);
    cudaGetSymbolAddress((void**)&vp, g_V);
    cudaGetSymbolAddress((void**)&cp, g_C);
    cudaGetSymbolAddress((void**)&xhi, g_Xhi);
    cudaGetSymbolAddress((void**)&xlo, g_Xlo);
    cudaGetSymbolAddress((void**)&chi, g_Chi);
    cudaGetSymbolAddress((void**)&clo, g_Clo);
    cudaGetSymbolAddress((void**)&whi, g_Whi);
    cudaGetSymbolAddress((void**)&wlo, g_Wlo);

    cudaFuncSetAttribute(tc_gemm, cudaFuncAttributeMaxDynamicSharedMemorySize, GT_SMEM);
    cudaFuncSetAttribute(attn_kernel, cudaFuncAttributeMaxDynamicSharedMemorySize, ATTN_SMEM);

    // prep: splits + transposed weights + rope table
    split_kernel<<<(MM * HH / 4 + 255) / 256, 256>>>(X, xhi, xlo, MM * HH / 4);
    wsplit_kernel<<<dim3(HH / 32, HH / 32, 4), dim3(32, 8)>>>(Wq, Wk, Wv, Wo);
    rope_table_kernel<<<(SS * 32 + 255) / 256, 256>>>();

    // projections (mma.sync bf16x3)
    dim3 gg(HH / 128, MM / 128);
    tc_gemm<<<gg, 256, GT_SMEM>>>(xhi, xlo, whi + 0 * (size_t)HH * HH, wlo + 0 * (size_t)HH * HH, bq, qp);
    tc_gemm<<<gg, 256, GT_SMEM>>>(xhi, xlo, whi + 1 * (size_t)HH * HH, wlo + 1 * (size_t)HH * HH, bk, kp);
    tc_gemm<<<gg, 256, GT_SMEM>>>(xhi, xlo, whi + 2 * (size_t)HH * HH, wlo + 2 * (size_t)HH * HH, bv, vp);

    rope_apply_kernel<<<(MM * NHEAD * 32 + 255) / 256, 256>>>(qp, kp);

    attn_kernel<<<dim3(SS / 64, NHEAD, BB), 256, ATTN_SMEM>>>(qp, kp, vp, mask, cp);

    // output projection
    split_kernel<<<(MM * HH / 4 + 255) / 256, 256>>>(cp, chi, clo, MM * HH / 4);
    tc_gemm<<<gg, 256, GT_SMEM>>>(chi, clo, whi + 3 * (size_t)HH * HH, wlo + 3 * (size_t)HH * HH, bo, out);
}

// round 6
// speedup vs baseline: 1.8431x; 1.8431x over previous
#include <cuda_runtime.h>
#include <cuda_bf16.h>
#include <math.h>
#include <stdint.h>

// Problem dims (fixed by the dataset)
#define BB 2
#define SS 2048
#define HH 1024
#define NHEAD 16
#define HD 64
#define MM (BB*SS)          // 4096 rows

// ---------------------------------------------------------------------------
// Scratch (device globals: allocation-free rule)
// ---------------------------------------------------------------------------
__device__ float g_Q[MM * HH];
__device__ float g_K[MM * HH];
__device__ float g_V[MM * HH];
__device__ float g_C[MM * HH];
__device__ float g_cos[SS * 32];
__device__ float g_sin[SS * 32];
__device__ __nv_bfloat16 g_Xhi[MM * HH];
__device__ __nv_bfloat16 g_Xlo[MM * HH];
__device__ __nv_bfloat16 g_Chi[MM * HH];
__device__ __nv_bfloat16 g_Clo[MM * HH];
__device__ __nv_bfloat16 g_Whi[4 * HH * HH];   // W^T hi, [N,K] per weight
__device__ __nv_bfloat16 g_Wlo[4 * HH * HH];   // W^T lo
__device__ __nv_bfloat16 g_Qhi[MM * HH];
__device__ __nv_bfloat16 g_Qlo[MM * HH];
__device__ __nv_bfloat16 g_Khi[MM * HH];
__device__ __nv_bfloat16 g_Klo[MM * HH];
__device__ __nv_bfloat16 g_Vhi[MM * HH];
__device__ __nv_bfloat16 g_Vlo[MM * HH];

// ---------------------------------------------------------------------------
// PTX helpers (sm_80-baseline features only: ldmatrix / mma.sync / cp.async)
// ---------------------------------------------------------------------------
__device__ __forceinline__ uint32_t smem_u32(const void* p) {
    uint32_t a;
    asm("{ .reg .u64 t; cvta.to.shared.u64 t, %1; cvt.u32.u64 %0, t; }" : "=r"(a) : "l"(p));
    return a;
}
#define CP_ASYNC16(s, g) \
    asm volatile("cp.async.cg.shared.global [%0], [%1], 16;" :: "r"(s), "l"(g))
#define CP_COMMIT() asm volatile("cp.async.commit_group;" ::: "memory")
#define CP_WAIT1()  asm volatile("cp.async.wait_group 1;" ::: "memory")
#define CP_WAIT0()  asm volatile("cp.async.wait_group 0;" ::: "memory")

__device__ __forceinline__ void ldsm_x4(uint32_t* r, uint32_t addr) {
    asm volatile("ldmatrix.sync.aligned.m8n8.x4.shared.b16 {%0,%1,%2,%3}, [%4];"
                 : "=r"(r[0]), "=r"(r[1]), "=r"(r[2]), "=r"(r[3]) : "r"(addr));
}
__device__ __forceinline__ void ldsm_x2(uint32_t* r, uint32_t addr) {
    asm volatile("ldmatrix.sync.aligned.m8n8.x2.shared.b16 {%0,%1}, [%2];"
                 : "=r"(r[0]), "=r"(r[1]) : "r"(addr));
}
__device__ __forceinline__ void ldsm_x2t(uint32_t* r, uint32_t addr) {
    asm volatile("ldmatrix.sync.aligned.m8n8.x2.trans.shared.b16 {%0,%1}, [%2];"
                 : "=r"(r[0]), "=r"(r[1]) : "r"(addr));
}
__device__ __forceinline__ void mma_bf16(float* c, const uint32_t* a, const uint32_t* b) {
    asm volatile("mma.sync.aligned.m16n8k16.row.col.f32.bf16.bf16.f32 "
                 "{%0,%1,%2,%3}, {%4,%5,%6,%7}, {%8,%9}, {%0,%1,%2,%3};"
                 : "+f"(c[0]), "+f"(c[1]), "+f"(c[2]), "+f"(c[3])
                 : "r"(a[0]), "r"(a[1]), "r"(a[2]), "r"(a[3]), "r"(b[0]), "r"(b[1]));
}

// ---------------------------------------------------------------------------
// Prep: fp32 -> (hi, lo) bf16 split
// ---------------------------------------------------------------------------
__global__ void split_kernel(const float* __restrict__ x,
                             __nv_bfloat16* __restrict__ hi,
                             __nv_bfloat16* __restrict__ lo, int n4)
{
    int i = blockIdx.x * blockDim.x + threadIdx.x;
    if (i >= n4) return;
    float4 v = reinterpret_cast<const float4*>(x)[i];
    __nv_bfloat16 h[4], l[4];
    float f[4] = {v.x, v.y, v.z, v.w};
    #pragma unroll
    for (int j = 0; j < 4; j++) {
        h[j] = __float2bfloat16(f[j]);
        l[j] = __float2bfloat16(f[j] - __bfloat162float(h[j]));
    }
    reinterpret_cast<ushort4*>(hi)[i] = make_ushort4(
        __bfloat16_as_ushort(h[0]), __bfloat16_as_ushort(h[1]),
        __bfloat16_as_ushort(h[2]), __bfloat16_as_ushort(h[3]));
    reinterpret_cast<ushort4*>(lo)[i] = make_ushort4(
        __bfloat16_as_ushort(l[0]), __bfloat16_as_ushort(l[1]),
        __bfloat16_as_ushort(l[2]), __bfloat16_as_ushort(l[3]));
}

// Transpose + split 4 weights: W[k,n] -> WT[n,k] hi/lo
__global__ void wsplit_kernel(const float* __restrict__ W0, const float* __restrict__ W1,
                              const float* __restrict__ W2, const float* __restrict__ W3)
{
    __shared__ float t[32][33];
    int w = blockIdx.z;
    const float* W = (w == 0) ? W0 : (w == 1) ? W1 : (w == 2) ? W2 : W3;
    int bn = blockIdx.x * 32;   // n block
    int bk = blockIdx.y * 32;   // k block
    int x = threadIdx.x, y = threadIdx.y;   // 32 x 8
    #pragma unroll
    for (int j = 0; j < 32; j += 8)
        t[y + j][x] = W[(size_t)(bk + y + j) * HH + bn + x];
    __syncthreads();
    size_t base = (size_t)w * HH * HH;
    #pragma unroll
    for (int j = 0; j < 32; j += 8) {
        float v = t[x][y + j];
        __nv_bfloat16 h = __float2bfloat16(v);
        __nv_bfloat16 l = __float2bfloat16(v - __bfloat162float(h));
        size_t o = base + (size_t)(bn + y + j) * HH + bk + x;
        g_Whi[o] = h;
        g_Wlo[o] = l;
    }
}

// ---------------------------------------------------------------------------
// Tensor-core GEMM (bf16x3 via mma.sync) — unchanged from R5 (verified)
// ---------------------------------------------------------------------------
#define TILE_E   (128 * 40)
#define STAGE_E  (4 * TILE_E)
#define GT_SMEM  (2 * STAGE_E * 2)

__global__ void __launch_bounds__(256) tc_gemm(
    const __nv_bfloat16* __restrict__ Ahi, const __nv_bfloat16* __restrict__ Alo,
    const __nv_bfloat16* __restrict__ Bhi, const __nv_bfloat16* __restrict__ Blo,
    const float* __restrict__ bias, float* __restrict__ C)
{
    extern __shared__ __nv_bfloat16 sm[];
    const int tid  = threadIdx.x;
    const int lane = tid & 31;
    const int w    = tid >> 5;
    const int wm   = (w & 1) * 64;
    const int wn   = (w >> 1) * 32;
    const int rowBase = blockIdx.y * 128;
    const int colBase = blockIdx.x * 128;

    const uint32_t sb = smem_u32(sm);

    const __nv_bfloat16* gsel[4] = {
        Ahi + (size_t)rowBase * HH, Alo + (size_t)rowBase * HH,
        Bhi + (size_t)colBase * HH, Blo + (size_t)colBase * HH };

    auto issue = [&](int st, int k0) {
        uint32_t sbase = sb + (uint32_t)(st * STAGE_E * 2);
        #pragma unroll
        for (int t = 0; t < 8; t++) {
            int i    = t * 256 + tid;
            int tile = i >> 9;
            int r    = (i >> 2) & 127;
            int c    = i & 3;
            uint32_t sa = sbase + (uint32_t)((tile * TILE_E + r * 40 + c * 8) * 2);
            const __nv_bfloat16* ga = gsel[tile] + (size_t)r * HH + k0 + c * 8;
            CP_ASYNC16(sa, ga);
        }
    };

    float acc[4][4][4];
    #pragma unroll
    for (int mt = 0; mt < 4; mt++)
        #pragma unroll
        for (int nt = 0; nt < 4; nt++)
            #pragma unroll
            for (int q = 0; q < 4; q++) acc[mt][nt][q] = 0.0f;

    issue(0, 0);
    CP_COMMIT();

    const int nIter = HH / 32;
    for (int it = 0; it < nIter; it++) {
        if (it + 1 < nIter) issue((it + 1) & 1, (it + 1) * 32);
        CP_COMMIT();
        CP_WAIT1();
        __syncthreads();

        uint32_t stage = sb + (uint32_t)((it & 1) * STAGE_E * 2);
        #pragma unroll
        for (int ks = 0; ks < 32; ks += 16) {
            #pragma unroll
            for (int combo = 0; combo < 3; combo++) {
                const int selA = (combo == 2) ? 1 : 0;
                const int selB = (combo == 1) ? 1 : 0;
                uint32_t abase = stage + (uint32_t)(selA * TILE_E * 2);
                uint32_t bbase = stage + (uint32_t)((2 + selB) * TILE_E * 2);

                uint32_t a[4][4];
                #pragma unroll
                for (int mt = 0; mt < 4; mt++) {
                    uint32_t addr = abase + (uint32_t)(((wm + mt * 16 + (lane & 15)) * 40
                                     + ks + ((lane >> 4) << 3)) * 2);
                    ldsm_x4(a[mt], addr);
                }
                #pragma unroll
                for (int nt = 0; nt < 4; nt++) {
                    uint32_t b[2];
                    uint32_t addr = bbase + (uint32_t)(((wn + nt * 8 + (lane & 7)) * 40
                                     + ks + (((lane >> 3) & 1) << 3)) * 2);
                    ldsm_x2(b, addr);
                    #pragma unroll
                    for (int mt = 0; mt < 4; mt++)
                        mma_bf16(acc[mt][nt], a[mt], b);
                }
            }
        }
        __syncthreads();
    }

    #pragma unroll
    for (int mt = 0; mt < 4; mt++) {
        int r0 = rowBase + wm + mt * 16 + (lane >> 2);
        #pragma unroll
        for (int nt = 0; nt < 4; nt++) {
            int cc = colBase + wn + nt * 8 + (lane & 3) * 2;
            float b0 = bias[cc], b1 = bias[cc + 1];
            float2 v0 = make_float2(acc[mt][nt][0] + b0, acc[mt][nt][1] + b1);
            float2 v1 = make_float2(acc[mt][nt][2] + b0, acc[mt][nt][3] + b1);
            *reinterpret_cast<float2*>(&C[(size_t)r0 * HH + cc]) = v0;
            *reinterpret_cast<float2*>(&C[(size_t)(r0 + 8) * HH + cc]) = v1;
        }
    }
}

// ---------------------------------------------------------------------------
// RoPE table
// ---------------------------------------------------------------------------
__global__ void rope_table_kernel()
{
    int i = blockIdx.x * blockDim.x + threadIdx.x;
    if (i >= SS * 32) return;
    int s = i >> 5;
    int d = i & 31;
    float inv = 1.0f / powf(10000.0f, (float)d / 32.0f);
    float th  = (float)s * inv;
    g_cos[i] = (float)cos((double)th);
    g_sin[i] = (float)sin((double)th);
}

// RoPE + bf16 hi/lo split of Q and K in one pass
__global__ void rope_split_kernel(const float* __restrict__ Q, const float* __restrict__ K)
{
    int idx = blockIdx.x * blockDim.x + threadIdx.x;
    const int total = MM * NHEAD * 32;
    if (idx >= total) return;
    int d   = idx & 31;
    int h   = (idx >> 5) & 15;
    int r   = idx >> 9;
    int s   = r & (SS - 1);
    float c  = g_cos[s * 32 + d];
    float sn = g_sin[s * 32 + d];
    size_t base = (size_t)r * HH + h * HD + d;

    float q0 = Q[base], q1 = Q[base + 32];
    float k0 = K[base], k1 = K[base + 32];
    float oq0 = q0 * c - q1 * sn;
    float oq1 = q1 * c + q0 * sn;
    float ok0 = k0 * c - k1 * sn;
    float ok1 = k1 * c + k0 * sn;

    __nv_bfloat16 hq0 = __float2bfloat16(oq0);
    __nv_bfloat16 hq1 = __float2bfloat16(oq1);
    __nv_bfloat16 hk0 = __float2bfloat16(ok0);
    __nv_bfloat16 hk1 = __float2bfloat16(ok1);
    g_Qhi[base]      = hq0;  g_Qlo[base]      = __float2bfloat16(oq0 - __bfloat162float(hq0));
    g_Qhi[base + 32] = hq1;  g_Qlo[base + 32] = __float2bfloat16(oq1 - __bfloat162float(hq1));
    g_Khi[base]      = hk0;  g_Klo[base]      = __float2bfloat16(ok0 - __bfloat162float(hk0));
    g_Khi[base + 32] = hk1;  g_Klo[base + 32] = __float2bfloat16(ok1 - __bfloat162float(hk1));
}

// ---------------------------------------------------------------------------
// Tensor-core flash attention (bf16x3).
// CTA: 128 q-rows x (b,h). 8 warps, 16 rows each. K-tile = 64, double buffered.
// smem (bf16 elems, stride 72/row):
//   Qhi 0, Qlo 9216 | KV stages @18432 (per stage 18432: Kh,Kl,Vh,Vl 4608 each)
//   Phi 55296, Plo 64512 | pads (float) @ elem 73728 (2 x 64 floats)
// ---------------------------------------------------------------------------
#define AST 72
#define A_QH 0
#define A_QL 9216
#define A_KV 18432
#define A_KVSZ 18432
#define A_PH 55296
#define A_PL 64512
#define A_PAD 73728
#define ATTN2_SMEM (73728*2 + 2*64*4)

__global__ void __launch_bounds__(256) attn_tc(
    const __nv_bfloat16* __restrict__ Qhi, const __nv_bfloat16* __restrict__ Qlo,
    const __nv_bfloat16* __restrict__ Khi, const __nv_bfloat16* __restrict__ Klo,
    const __nv_bfloat16* __restrict__ Vhi, const __nv_bfloat16* __restrict__ Vlo,
    const float* __restrict__ mask, float* __restrict__ Ctx)
{
    extern __shared__ __nv_bfloat16 sm[];
    float* pads = reinterpret_cast<float*>(sm + A_PAD);

    const int b   = blockIdx.z;
    const int h   = blockIdx.y;
    const int qt  = gridDim.x - 1 - blockIdx.x;   // heavy tiles first
    const int q0  = qt * 128;
    const int tid  = threadIdx.x;
    const int lane = tid & 31;
    const int w    = tid >> 5;
    const int wm   = w * 16;

    const uint32_t sb = smem_u32(sm);
    const size_t rowG = (size_t)(b * SS);
    const size_t hoff = (size_t)h * HD;

    // ---- load Q tile (hi+lo): 2048 x 16B chunks
    {
        const __nv_bfloat16* qsel[2] = { Qhi + (rowG + q0) * HH + hoff,
                                         Qlo + (rowG + q0) * HH + hoff };
        #pragma unroll
        for (int t = 0; t < 8; t++) {
            int i   = t * 256 + tid;
            int arr = i >> 10;
            int r   = (i >> 3) & 127;
            int c   = i & 7;
            uint32_t sa = sb + (uint32_t)(((arr ? A_QL : A_QH) + r * AST + c * 8) * 2);
            CP_ASYNC16(sa, qsel[arr] + (size_t)r * HH + c * 8);
        }
    }

    const __nv_bfloat16* kvsel[4] = {
        Khi + rowG * HH + hoff, Klo + rowG * HH + hoff,
        Vhi + rowG * HH + hoff, Vlo + rowG * HH + hoff };
    const float* mb = mask + b * SS;

    auto issueKV = [&](int st, int k0) {
        uint32_t sbase = sb + (uint32_t)((A_KV + st * A_KVSZ) * 2);
        #pragma unroll
        for (int t = 0; t < 8; t++) {
            int i   = t * 256 + tid;
            int arr = i >> 9;
            int r   = (i >> 3) & 63;
            int c   = i & 7;
            uint32_t sa = sbase + (uint32_t)((arr * 4608 + r * AST + c * 8) * 2);
            CP_ASYNC16(sa, kvsel[arr] + (size_t)(k0 + r) * HH + c * 8);
        }
        if (tid < 64)
            pads[st * 64 + tid] = (1.0f - mb[k0 + tid]) * (-1e4f);
    };

    issueKV(0, 0);
    CP_COMMIT();

    float oacc[8][4];
    #pragma unroll
    for (int nt = 0; nt < 8; nt++)
        #pragma unroll
        for (int q = 0; q < 4; q++) oacc[nt][q] = 0.0f;
    float m0 = -1e30f, m1 = -1e30f, l0 = 0.0f, l1 = 0.0f;

    const int row0 = q0 + wm + (lane >> 2);
    const int row1 = row0 + 8;
    const int nkt  = (q0 + 128) / 64;

    for (int kt = 0; kt < nkt; kt++) {
        const int st = kt & 1;
        const int k0 = kt * 64;
        if (kt + 1 < nkt) {
            issueKV(st ^ 1, (kt + 1) * 64);
            CP_COMMIT();
            CP_WAIT1();
        } else {
            CP_WAIT0();
        }
        __syncthreads();

        const uint32_t kvb = sb + (uint32_t)((A_KV + st * A_KVSZ) * 2);

        // ---- S = Q K^T (bf16x3), warp computes 16 x 64
        float sacc[8][4];
        #pragma unroll
        for (int nt = 0; nt < 8; nt++)
            #pragma unroll
            for (int q = 0; q < 4; q++) sacc[nt][q] = 0.0f;

        #pragma unroll
        for (int ks = 0; ks < 4; ks++) {
            uint32_t ah[4], al[4];
            uint32_t aoff = (uint32_t)(((wm + (lane & 15)) * AST + ks * 16 + ((lane >> 4) << 3)) * 2);
            ldsm_x4(ah, sb + (uint32_t)(A_QH * 2) + aoff);
            ldsm_x4(al, sb + (uint32_t)(A_QL * 2) + aoff);
            #pragma unroll
            for (int nt = 0; nt < 8; nt++) {
                uint32_t bh[2], bl[2];
                uint32_t boff = (uint32_t)(((nt * 8 + (lane & 7)) * AST + ks * 16 + (((lane >> 3) & 1) << 3)) * 2);
                ldsm_x2(bh, kvb + boff);                          // Khi
                ldsm_x2(bl, kvb + (uint32_t)(4608 * 2) + boff);   // Klo
                mma_bf16(sacc[nt], ah, bh);
                mma_bf16(sacc[nt], ah, bl);
                mma_bf16(sacc[nt], al, bh);
            }
        }

        // ---- scale + pad + causal, online softmax
        const int colb = (lane & 3) * 2;
        float mx0 = -1e30f, mx1 = -1e30f;
        #pragma unroll
        for (int nt = 0; nt < 8; nt++) {
            int c0 = k0 + nt * 8 + colb;
            float p0 = pads[st * 64 + nt * 8 + colb];
            float p1 = pads[st * 64 + nt * 8 + colb + 1];
            float s0 = sacc[nt][0] * 0.125f + p0 + ((c0     > row0) ? -1e10f : 0.0f);
            float s1 = sacc[nt][1] * 0.125f + p1 + ((c0 + 1 > row0) ? -1e10f : 0.0f);
            float s2 = sacc[nt][2] * 0.125f + p0 + ((c0     > row1) ? -1e10f : 0.0f);
            float s3 = sacc[nt][3] * 0.125f + p1 + ((c0 + 1 > row1) ? -1e10f : 0.0f);
            sacc[nt][0] = s0; sacc[nt][1] = s1; sacc[nt][2] = s2; sacc[nt][3] = s3;
            mx0 = fmaxf(mx0, fmaxf(s0, s1));
            mx1 = fmaxf(mx1, fmaxf(s2, s3));
        }
        mx0 = fmaxf(mx0, __shfl_xor_sync(0xffffffffu, mx0, 1));
        mx0 = fmaxf(mx0, __shfl_xor_sync(0xffffffffu, mx0, 2));
        mx1 = fmaxf(mx1, __shfl_xor_sync(0xffffffffu, mx1, 1));
        mx1 = fmaxf(mx1, __shfl_xor_sync(0xffffffffu, mx1, 2));

        float mn0 = fmaxf(m0, mx0), mn1 = fmaxf(m1, mx1);
        float al0 = __expf(m0 - mn0), al1 = __expf(m1 - mn1);
        m0 = mn0; m1 = mn1;

        float sum0 = 0.0f, sum1 = 0.0f;
        uint32_t phb = sb + (uint32_t)(A_PH * 2);
        uint32_t plb = sb + (uint32_t)(A_PL * 2);
        int rl0 = wm + (lane >> 2);
        #pragma unroll
        for (int nt = 0; nt < 8; nt++) {
            float p0 = __expf(sacc[nt][0] - mn0);
            float p1 = __expf(sacc[nt][1] - mn0);
            float p2 = __expf(sacc[nt][2] - mn1);
            float p3 = __expf(sacc[nt][3] - mn1);
            sum0 += p0 + p1; sum1 += p2 + p3;
            __nv_bfloat16 h0 = __float2bfloat16(p0), h1 = __float2bfloat16(p1);
            __nv_bfloat16 h2 = __float2bfloat16(p2), h3 = __float2bfloat16(p3);
            __nv_bfloat162 hi01 = __nv_bfloat162(h0, h1);
            __nv_bfloat162 hi23 = __nv_bfloat162(h2, h3);
            __nv_bfloat162 lo01 = __nv_bfloat162(
                __float2bfloat16(p0 - __bfloat162float(h0)),
                __float2bfloat16(p1 - __bfloat162float(h1)));
            __nv_bfloat162 lo23 = __nv_bfloat162(
                __float2bfloat16(p2 - __bfloat162float(h2)),
                __float2bfloat16(p3 - __bfloat162float(h3)));
            uint32_t co = (uint32_t)((nt * 8 + colb) * 2);
            *reinterpret_cast<__nv_bfloat162*>(
                (char*)sm + (phb - sb) + rl0 * AST * 2 + co)       = hi01;
            *reinterpret_cast<__nv_bfloat162*>(
                (char*)sm + (phb - sb) + (rl0 + 8) * AST * 2 + co) = hi23;
            *reinterpret_cast<__nv_bfloat162*>(
                (char*)sm + (plb - sb) + rl0 * AST * 2 + co)       = lo01;
            *reinterpret_cast<__nv_bfloat162*>(
                (char*)sm + (plb - sb) + (rl0 + 8) * AST * 2 + co) = lo23;
        }
        sum0 += __shfl_xor_sync(0xffffffffu, sum0, 1);
        sum0 += __shfl_xor_sync(0xffffffffu, sum0, 2);
        sum1 += __shfl_xor_sync(0xffffffffu, sum1, 1);
        sum1 += __shfl_xor_sync(0xffffffffu, sum1, 2);
        l0 = l0 * al0 + sum0;
        l1 = l1 * al1 + sum1;
        #pragma unroll
        for (int nt = 0; nt < 8; nt++) {
            oacc[nt][0] *= al0; oacc[nt][1] *= al0;
            oacc[nt][2] *= al1; oacc[nt][3] *= al1;
        }
        __syncwarp();

        // ---- O += P V (bf16x3): warp's own 16 P rows only
        #pragma unroll
        for (int ks = 0; ks < 4; ks++) {
            uint32_t ah[4], al_[4];
            uint32_t aoff = (uint32_t)(((wm + (lane & 15)) * AST + ks * 16 + ((lane >> 4) << 3)) * 2);
            ldsm_x4(ah,  phb + aoff);
            ldsm_x4(al_, plb + aoff);
            #pragma unroll
            for (int nt = 0; nt < 8; nt++) {
                uint32_t bh[2], bl[2];
                uint32_t boff = (uint32_t)(((ks * 16 + (lane & 15)) * AST + nt * 8) * 2);
                ldsm_x2t(bh, kvb + (uint32_t)(9216 * 2) + boff);   // Vhi
                ldsm_x2t(bl, kvb + (uint32_t)(13824 * 2) + boff);  // Vlo
                mma_bf16(oacc[nt], ah,  bh);
                mma_bf16(oacc[nt], ah,  bl);
                mma_bf16(oacc[nt], al_, bh);
            }
        }
        __syncthreads();   // all warps done with KV stage st before overwrite
    }

    // ---- write ctx fp32
    float inv0 = 1.0f / l0, inv1 = 1.0f / l1;
    float* Cb = Ctx + rowG * HH + hoff;
    #pragma unroll
    for (int nt = 0; nt < 8; nt++) {
        int cc = nt * 8 + (lane & 3) * 2;
        float2 v0 = make_float2(oacc[nt][0] * inv0, oacc[nt][1] * inv0);
        float2 v1 = make_float2(oacc[nt][2] * inv1, oacc[nt][3] * inv1);
        *reinterpret_cast<float2*>(&Cb[(size_t)row0 * HH + cc]) = v0;
        *reinterpret_cast<float2*>(&Cb[(size_t)row1 * HH + cc]) = v1;
    }
}

// ---------------------------------------------------------------------------
// launcher
// ---------------------------------------------------------------------------
extern "C" void kernel_launch(void* const* d_in, const int* in_sizes, int n_in,
                              void* d_out, int out_size)
{
    const float* X    = (const float*)d_in[0];
    const float* mask = (const float*)d_in[1];
    const float* Wq   = (const float*)d_in[2];
    const float* bq   = (const float*)d_in[3];
    const float* Wk   = (const float*)d_in[4];
    const float* bk   = (const float*)d_in[5];
    const float* Wv   = (const float*)d_in[6];
    const float* bv   = (const float*)d_in[7];
    const float* Wo   = (const float*)d_in[8];
    const float* bo   = (const float*)d_in[9];
    float* out = (float*)d_out;

    float *qp, *kp, *vp, *cp;
    __nv_bfloat16 *xhi, *xlo, *chi, *clo, *whi, *wlo;
    __nv_bfloat16 *qhi, *qlo, *khi, *klo, *vhi, *vlo;
    cudaGetSymbolAddress((void**)&qp, g_Q);
    cudaGetSymbolAddress((void**)&kp, g_K);
    cudaGetSymbolAddress((void**)&vp, g_V);
    cudaGetSymbolAddress((void**)&cp, g_C);
    cudaGetSymbolAddress((void**)&xhi, g_Xhi);
    cudaGetSymbolAddress((void**)&xlo, g_Xlo);
    cudaGetSymbolAddress((void**)&chi, g_Chi);
    cudaGetSymbolAddress((void**)&clo, g_Clo);
    cudaGetSymbolAddress((void**)&whi, g_Whi);
    cudaGetSymbolAddress((void**)&wlo, g_Wlo);
    cudaGetSymbolAddress((void**)&qhi, g_Qhi);
    cudaGetSymbolAddress((void**)&qlo, g_Qlo);
    cudaGetSymbolAddress((void**)&khi, g_Khi);
    cudaGetSymbolAddress((void**)&klo, g_Klo);
    cudaGetSymbolAddress((void**)&vhi, g_Vhi);
    cudaGetSymbolAddress((void**)&vlo, g_Vlo);

    cudaFuncSetAttribute(tc_gemm, cudaFuncAttributeMaxDynamicSharedMemorySize, GT_SMEM);
    cudaFuncSetAttribute(attn_tc, cudaFuncAttributeMaxDynamicSharedMemorySize, ATTN2_SMEM);

    // prep
    split_kernel<<<(MM * HH / 4 + 255) / 256, 256>>>(X, xhi, xlo, MM * HH / 4);
    wsplit_kernel<<<dim3(HH / 32, HH / 32, 4), dim3(32, 8)>>>(Wq, Wk, Wv, Wo);
    rope_table_kernel<<<(SS * 32 + 255) / 256, 256>>>();

    // projections
    dim3 gg(HH / 128, MM / 128);
    tc_gemm<<<gg, 256, GT_SMEM>>>(xhi, xlo, whi + 0 * (size_t)HH * HH, wlo + 0 * (size_t)HH * HH, bq, qp);
    tc_gemm<<<gg, 256, GT_SMEM>>>(xhi, xlo, whi + 1 * (size_t)HH * HH, wlo + 1 * (size_t)HH * HH, bk, kp);
    tc_gemm<<<gg, 256, GT_SMEM>>>(xhi, xlo, whi + 2 * (size_t)HH * HH, wlo + 2 * (size_t)HH * HH, bv, vp);

    // rope + split Q/K, split V
    rope_split_kernel<<<(MM * NHEAD * 32 + 255) / 256, 256>>>(qp, kp);
    split_kernel<<<(MM * HH / 4 + 255) / 256, 256>>>(vp, vhi, vlo, MM * HH / 4);

    // tensor-core flash attention
    attn_tc<<<dim3(SS / 128, NHEAD, BB), 256, ATTN2_SMEM>>>(qhi, qlo, khi, klo, vhi, vlo, mask, cp);

    // output projection
    split_kernel<<<(MM * HH / 4 + 255) / 256, 256>>>(cp, chi, clo, MM * HH / 4);
    tc_gemm<<<gg, 256, GT_SMEM>>>(chi, clo, whi + 3 * (size_t)HH * HH, wlo + 3 * (size_t)HH * HH, bo, out);
}